// round 1
// baseline (speedup 1.0000x reference)
#include <cuda_runtime.h>
#include <math.h>

// ---------------------------------------------------------------------------
// GroupedQueryAttention: x[2,2048,2048], Wq[2048,2048], Wk/Wv[2048,512],
// Wo[2048,2048]. H=32 heads, KVH=8, HD=64. fp32 baseline.
// Stages: QKV proj (SGEMM x3) -> flash attention -> O proj (SGEMM).
// ---------------------------------------------------------------------------

// Scratch (allocation-free: device globals)
__device__ float g_Q[4096 * 2048];   // [b*s][h*64]
__device__ float g_K[4096 * 512];    // [b*s][kvh*64]
__device__ float g_V[4096 * 512];
__device__ float g_C[4096 * 2048];   // attention context

// ---------------------------------------------------------------------------
// SGEMM: C[M,N] = A[M,K] @ B[K,N], all row-major fp32.
// BM=BN=128, BK=8, 256 threads, 8x8 per thread (split 4+4 to keep smem reads
// conflict-free: frag loads are float4 at [tr*4] and [64+tr*4]).
// M,N multiples of 128; K multiple of 8 (true for all our shapes).
// ---------------------------------------------------------------------------
__global__ void __launch_bounds__(256) sgemm128(const float* __restrict__ A,
                                                const float* __restrict__ Bm,
                                                float* __restrict__ C,
                                                int M, int N, int K) {
    __shared__ float As[8][132];   // transposed A tile, pad 132 -> conflict-free stores
    __shared__ float Bs[8][128];

    const int tid = threadIdx.x;
    const int tr = tid >> 4;       // 0..15 (row group)
    const int tc = tid & 15;       // 0..15 (col group)
    const int bm = blockIdx.y * 128;
    const int bn = blockIdx.x * 128;

    const float* Ag = A + (size_t)(bm + (tid >> 1)) * K + (tid & 1) * 4;
    const float* Bg = Bm + (size_t)(tid >> 5) * N + bn + (tid & 31) * 4;

    float acc[8][8];
#pragma unroll
    for (int i = 0; i < 8; i++)
#pragma unroll
        for (int j = 0; j < 8; j++) acc[i][j] = 0.0f;

    for (int kt = 0; kt < K; kt += 8) {
        float4 av = *(const float4*)(Ag + kt);
        float4 bv = *(const float4*)(Bg + (size_t)kt * N);
        __syncthreads();
        {
            int arow = (tid & 1) * 4;
            int acol = tid >> 1;
            As[arow + 0][acol] = av.x;
            As[arow + 1][acol] = av.y;
            As[arow + 2][acol] = av.z;
            As[arow + 3][acol] = av.w;
            *(float4*)&Bs[tid >> 5][(tid & 31) * 4] = bv;
        }
        __syncthreads();
#pragma unroll
        for (int k = 0; k < 8; k++) {
            float a[8], b[8];
            *(float4*)(a)     = *(const float4*)&As[k][tr * 4];
            *(float4*)(a + 4) = *(const float4*)&As[k][64 + tr * 4];
            *(float4*)(b)     = *(const float4*)&Bs[k][tc * 4];
            *(float4*)(b + 4) = *(const float4*)&Bs[k][64 + tc * 4];
#pragma unroll
            for (int i = 0; i < 8; i++)
#pragma unroll
                for (int j = 0; j < 8; j++)
                    acc[i][j] = fmaf(a[i], b[j], acc[i][j]);
        }
    }

#pragma unroll
    for (int i = 0; i < 8; i++) {
        int r = bm + ((i < 4) ? (tr * 4 + i) : (64 + tr * 4 + i - 4));
        float* Cr = C + (size_t)r * N + bn;
        *(float4*)(Cr + tc * 4) =
            make_float4(acc[i][0], acc[i][1], acc[i][2], acc[i][3]);
        *(float4*)(Cr + 64 + tc * 4) =
            make_float4(acc[i][4], acc[i][5], acc[i][6], acc[i][7]);
    }
}

// ---------------------------------------------------------------------------
// Flash attention: one CTA = 64 queries of one (batch, head).
// grid = (S/64 = 32, B*H = 64). 256 threads as (ty,tx) = 16x16; each thread
// owns a 4x4 microtile: rows q = ty*4+i, cols tx*4+j.
// D = head_dim = 64, kv tile = 64. Online softmax in registers.
// smem layouts chosen for bank behavior (see strides).
// ---------------------------------------------------------------------------
__global__ void __launch_bounds__(256) attn64(const float* __restrict__ Q,
                                              const float* __restrict__ K,
                                              const float* __restrict__ V,
                                              float* __restrict__ O) {
    extern __shared__ float smem[];
    float* Qt = smem;                 // [d][q]  stride 68 (float4 frag loads, broadcast)
    float* Ks = Qt + 64 * 68;         // [k][d]  stride 65 (scalar reads, 2-way worst)
    float* Vs = Ks + 64 * 65;         // [k][d]  stride 68 (float4 reads, conflict-free)
    float* Ps = Vs + 64 * 68;         // [k][q]  stride 65

    const int tid = threadIdx.x;
    const int ty = tid >> 4;          // 0..15
    const int tx = tid & 15;          // 0..15
    const int qt = blockIdx.x;        // query tile
    const int bh = blockIdx.y;
    const int b = bh >> 5, h = bh & 31, kvh = h >> 2;

    const float* Qg = Q + (size_t)(b * 2048 + qt * 64) * 2048 + h * 64;
    const float* Kg = K + (size_t)(b * 2048) * 512 + kvh * 64;
    const float* Vg = V + (size_t)(b * 2048) * 512 + kvh * 64;

    const float scale = 0.125f;  // 1/sqrt(64), folded into Q at load

    // Load Q tile, transposed + pre-scaled
#pragma unroll
    for (int it = 0; it < 4; it++) {
        int idx = tid + it * 256;                 // 1024 float4s total
        int q = idx >> 4;
        int d4 = (idx & 15) * 4;
        float4 v = *(const float4*)(Qg + (size_t)q * 2048 + d4);
        Qt[(d4 + 0) * 68 + q] = v.x * scale;
        Qt[(d4 + 1) * 68 + q] = v.y * scale;
        Qt[(d4 + 2) * 68 + q] = v.z * scale;
        Qt[(d4 + 3) * 68 + q] = v.w * scale;
    }

    float o[4][4];
    float m[4], l[4];
#pragma unroll
    for (int i = 0; i < 4; i++) {
        m[i] = -1e30f;
        l[i] = 0.0f;
#pragma unroll
        for (int j = 0; j < 4; j++) o[i][j] = 0.0f;
    }

    for (int kt = 0; kt < 32; kt++) {
        __syncthreads();  // previous tile's smem reads complete
        // Load K, V tiles
#pragma unroll
        for (int it = 0; it < 4; it++) {
            int idx = tid + it * 256;
            int r = idx >> 4;
            int c4 = (idx & 15) * 4;
            float4 kv = *(const float4*)(Kg + (size_t)(kt * 64 + r) * 512 + c4);
            Ks[r * 65 + c4 + 0] = kv.x;
            Ks[r * 65 + c4 + 1] = kv.y;
            Ks[r * 65 + c4 + 2] = kv.z;
            Ks[r * 65 + c4 + 3] = kv.w;
            float4 vv = *(const float4*)(Vg + (size_t)(kt * 64 + r) * 512 + c4);
            *(float4*)(Vs + r * 68 + c4) = vv;
        }
        __syncthreads();

        // S = (Q*scale) @ K^T : 4x4 per thread, dot over d
        float s[4][4];
#pragma unroll
        for (int i = 0; i < 4; i++)
#pragma unroll
            for (int j = 0; j < 4; j++) s[i][j] = 0.0f;

        const float* kb = Ks + (tx * 4) * 65;
#pragma unroll
        for (int d = 0; d < 64; d++) {
            float4 qv = *(const float4*)(Qt + d * 68 + ty * 4);
            float qa[4] = {qv.x, qv.y, qv.z, qv.w};
            float ka[4];
            ka[0] = kb[d];
            ka[1] = kb[65 + d];
            ka[2] = kb[130 + d];
            ka[3] = kb[195 + d];
#pragma unroll
            for (int i = 0; i < 4; i++)
#pragma unroll
                for (int j = 0; j < 4; j++)
                    s[i][j] = fmaf(qa[i], ka[j], s[i][j]);
        }

        // Online softmax (row stats reduced across tx lanes via shfl)
#pragma unroll
        for (int i = 0; i < 4; i++) {
            float rm = fmaxf(fmaxf(s[i][0], s[i][1]), fmaxf(s[i][2], s[i][3]));
#pragma unroll
            for (int off = 8; off >= 1; off >>= 1)
                rm = fmaxf(rm, __shfl_xor_sync(0xffffffffu, rm, off));
            float mn = fmaxf(m[i], rm);
            float alpha = __expf(m[i] - mn);
            m[i] = mn;
            float rs = 0.0f;
#pragma unroll
            for (int j = 0; j < 4; j++) {
                float p = __expf(s[i][j] - mn);
                s[i][j] = p;
                rs += p;
            }
#pragma unroll
            for (int off = 8; off >= 1; off >>= 1)
                rs += __shfl_xor_sync(0xffffffffu, rs, off);
            l[i] = l[i] * alpha + rs;
#pragma unroll
            for (int j = 0; j < 4; j++) o[i][j] *= alpha;
        }

        // P -> smem (layout [kj][q], stride 65)
#pragma unroll
        for (int j = 0; j < 4; j++)
#pragma unroll
            for (int i = 0; i < 4; i++)
                Ps[(tx * 4 + j) * 65 + ty * 4 + i] = s[i][j];
        __syncthreads();

        // O += P @ V : dot over kj
#pragma unroll
        for (int kj = 0; kj < 64; kj++) {
            float4 vv = *(const float4*)(Vs + kj * 68 + tx * 4);
            float va[4] = {vv.x, vv.y, vv.z, vv.w};
            float p0 = Ps[kj * 65 + ty * 4 + 0];
            float p1 = Ps[kj * 65 + ty * 4 + 1];
            float p2 = Ps[kj * 65 + ty * 4 + 2];
            float p3 = Ps[kj * 65 + ty * 4 + 3];
#pragma unroll
            for (int j = 0; j < 4; j++) {
                o[0][j] = fmaf(p0, va[j], o[0][j]);
                o[1][j] = fmaf(p1, va[j], o[1][j]);
                o[2][j] = fmaf(p2, va[j], o[2][j]);
                o[3][j] = fmaf(p3, va[j], o[3][j]);
            }
        }
    }

    // Normalize + write context [b*s][h*64+d]
    float* Og = O + (size_t)(b * 2048 + qt * 64) * 2048 + h * 64;
#pragma unroll
    for (int i = 0; i < 4; i++) {
        float inv = 1.0f / l[i];
        float4 v = make_float4(o[i][0] * inv, o[i][1] * inv,
                               o[i][2] * inv, o[i][3] * inv);
        *(float4*)(Og + (size_t)(ty * 4 + i) * 2048 + tx * 4) = v;
    }
}

// ---------------------------------------------------------------------------
// Launch
// ---------------------------------------------------------------------------
extern "C" void kernel_launch(void* const* d_in, const int* in_sizes, int n_in,
                              void* d_out, int out_size) {
    const float* x  = (const float*)d_in[0];
    const float* Wq = (const float*)d_in[1];
    const float* Wk = (const float*)d_in[2];
    const float* Wv = (const float*)d_in[3];
    const float* Wo = (const float*)d_in[4];
    float* out = (float*)d_out;

    float *pQ, *pK, *pV, *pC;
    cudaGetSymbolAddress((void**)&pQ, g_Q);
    cudaGetSymbolAddress((void**)&pK, g_K);
    cudaGetSymbolAddress((void**)&pV, g_V);
    cudaGetSymbolAddress((void**)&pC, g_C);

    const int ATTN_SMEM = (64 * 68 + 64 * 65 + 64 * 68 + 64 * 65) * 4;  // 68096 B
    cudaFuncSetAttribute(attn64, cudaFuncAttributeMaxDynamicSharedMemorySize,
                         ATTN_SMEM);

    // QKV projections
    sgemm128<<<dim3(16, 32), 256>>>(x, Wq, pQ, 4096, 2048, 2048);
    sgemm128<<<dim3(4, 32), 256>>>(x, Wk, pK, 4096, 512, 2048);
    sgemm128<<<dim3(4, 32), 256>>>(x, Wv, pV, 4096, 512, 2048);

    // Attention
    attn64<<<dim3(32, 64), 256, ATTN_SMEM>>>(pQ, pK, pV, pC);

    // Output projection
    sgemm128<<<dim3(16, 32), 256>>>(pC, Wo, out, 4096, 2048, 2048);
}

// round 2
// speedup vs baseline: 1.0318x; 1.0318x over previous
#include <cuda_runtime.h>
#include <math.h>

// ---------------------------------------------------------------------------
// GroupedQueryAttention: x[2,2048,2048], Wq[2048,2048], Wk/Wv[2048,512],
// Wo[2048,2048]. H=32, KVH=8, HD=64.
// fp32 via packed fma.rn.f32x2 (2x FFMA throughput on sm_103a, exact fp32).
// ---------------------------------------------------------------------------

typedef unsigned long long ull;

__device__ __forceinline__ ull pack2(float lo, float hi) {
    ull r;
    asm("mov.b64 %0, {%1, %2};" : "=l"(r) : "f"(lo), "f"(hi));
    return r;
}
__device__ __forceinline__ ull dup2(float v) {
    ull r;
    asm("mov.b64 %0, {%1, %1};" : "=l"(r) : "f"(v));
    return r;
}
__device__ __forceinline__ ull fma2(ull a, ull b, ull c) {
    ull d;
    asm("fma.rn.f32x2 %0, %1, %2, %3;" : "=l"(d) : "l"(a), "l"(b), "l"(c));
    return d;
}
__device__ __forceinline__ ull mul2(ull a, ull b) {
    ull d;
    asm("mul.rn.f32x2 %0, %1, %2;" : "=l"(d) : "l"(a), "l"(b));
    return d;
}
__device__ __forceinline__ float2 unpk2(ull v) {
    float2 f;
    asm("mov.b64 {%0, %1}, %2;" : "=f"(f.x), "=f"(f.y) : "l"(v));
    return f;
}

// Scratch (allocation-free: device globals)
__device__ float g_Q[4096 * 2048];   // [b*s][h*64]
__device__ float g_K[4096 * 512];    // [b*s][kvh*64]
__device__ float g_V[4096 * 512];
__device__ float g_C[4096 * 2048];   // attention context

// ---------------------------------------------------------------------------
// SGEMM: C[M,N] = A[M,K] @ B[K,N], row-major fp32, f32x2 inner product.
// BM=BN=128, BK=8, 256 threads, 8x8 per thread (as 8x4 f32x2 pairs).
// ---------------------------------------------------------------------------
__global__ void __launch_bounds__(256) sgemm128(const float* __restrict__ A,
                                                const float* __restrict__ Bm,
                                                float* __restrict__ C,
                                                int M, int N, int K) {
    __shared__ float As[8][132];   // transposed A tile
    __shared__ float Bs[8][128];

    const int tid = threadIdx.x;
    const int tr = tid >> 4;       // 0..15
    const int tc = tid & 15;       // 0..15
    const int bm = blockIdx.y * 128;
    const int bn = blockIdx.x * 128;

    const float* Ag = A + (size_t)(bm + (tid >> 1)) * K + (tid & 1) * 4;
    const float* Bg = Bm + (size_t)(tid >> 5) * N + bn + (tid & 31) * 4;

    ull acc2[8][4];
#pragma unroll
    for (int i = 0; i < 8; i++)
#pragma unroll
        for (int j = 0; j < 4; j++) acc2[i][j] = 0ull;

    for (int kt = 0; kt < K; kt += 8) {
        float4 av = *(const float4*)(Ag + kt);
        float4 bv = *(const float4*)(Bg + (size_t)kt * N);
        __syncthreads();
        {
            int arow = (tid & 1) * 4;
            int acol = tid >> 1;
            As[arow + 0][acol] = av.x;
            As[arow + 1][acol] = av.y;
            As[arow + 2][acol] = av.z;
            As[arow + 3][acol] = av.w;
            *(float4*)&Bs[tid >> 5][(tid & 31) * 4] = bv;
        }
        __syncthreads();
#pragma unroll
        for (int k = 0; k < 8; k++) {
            float a[8];
            *(float4*)(a)     = *(const float4*)&As[k][tr * 4];
            *(float4*)(a + 4) = *(const float4*)&As[k][64 + tr * 4];
            ull ad[8];
#pragma unroll
            for (int i = 0; i < 8; i++) ad[i] = dup2(a[i]);
            ull b2[4];
            b2[0] = *(const ull*)&Bs[k][tc * 4];
            b2[1] = *(const ull*)&Bs[k][tc * 4 + 2];
            b2[2] = *(const ull*)&Bs[k][64 + tc * 4];
            b2[3] = *(const ull*)&Bs[k][64 + tc * 4 + 2];
#pragma unroll
            for (int i = 0; i < 8; i++)
#pragma unroll
                for (int j = 0; j < 4; j++)
                    acc2[i][j] = fma2(ad[i], b2[j], acc2[i][j]);
        }
    }

#pragma unroll
    for (int i = 0; i < 8; i++) {
        int r = bm + ((i < 4) ? (tr * 4 + i) : (64 + tr * 4 + i - 4));
        float* Cr = C + (size_t)r * N + bn;
        float2 c0 = unpk2(acc2[i][0]), c1 = unpk2(acc2[i][1]);
        float2 c2 = unpk2(acc2[i][2]), c3 = unpk2(acc2[i][3]);
        *(float4*)(Cr + tc * 4)      = make_float4(c0.x, c0.y, c1.x, c1.y);
        *(float4*)(Cr + 64 + tc * 4) = make_float4(c2.x, c2.y, c3.x, c3.y);
    }
}

// ---------------------------------------------------------------------------
// Flash attention: one CTA = 64 queries of one (batch, head).
// grid = (32, 64). 256 threads (ty,tx)=16x16, 4x4 microtile, f32x2 math.
// K stored TRANSPOSED in smem ([d][k]) so QK^T reads K as 64-bit vectors.
// ---------------------------------------------------------------------------
__global__ void __launch_bounds__(256) attn64(const float* __restrict__ Q,
                                              const float* __restrict__ K,
                                              const float* __restrict__ V,
                                              float* __restrict__ O) {
    extern __shared__ float smem[];
    float* Qt = smem;                 // [d][q]  stride 68
    float* Kt = Qt + 64 * 68;         // [d][k]  stride 68 (transposed K)
    float* Vs = Kt + 64 * 68;         // [k][d]  stride 68
    float* Ps = Vs + 64 * 68;         // [k][q]  stride 65

    const int tid = threadIdx.x;
    const int ty = tid >> 4;
    const int tx = tid & 15;
    const int qt = blockIdx.x;
    const int bh = blockIdx.y;
    const int b = bh >> 5, h = bh & 31, kvh = h >> 2;

    const float* Qg = Q + (size_t)(b * 2048 + qt * 64) * 2048 + h * 64;
    const float* Kg = K + (size_t)(b * 2048) * 512 + kvh * 64;
    const float* Vg = V + (size_t)(b * 2048) * 512 + kvh * 64;

    const float scale = 0.125f;  // 1/sqrt(64), folded into Q

    // Load Q tile, transposed + pre-scaled
#pragma unroll
    for (int it = 0; it < 4; it++) {
        int idx = tid + it * 256;
        int q = idx >> 4;
        int d4 = (idx & 15) * 4;
        float4 v = *(const float4*)(Qg + (size_t)q * 2048 + d4);
        Qt[(d4 + 0) * 68 + q] = v.x * scale;
        Qt[(d4 + 1) * 68 + q] = v.y * scale;
        Qt[(d4 + 2) * 68 + q] = v.z * scale;
        Qt[(d4 + 3) * 68 + q] = v.w * scale;
    }

    ull o2[4][2];
    float m[4], l[4];
#pragma unroll
    for (int i = 0; i < 4; i++) {
        m[i] = -1e30f;
        l[i] = 0.0f;
        o2[i][0] = 0ull;
        o2[i][1] = 0ull;
    }

    const int kcol = tx * 4;

    for (int kt = 0; kt < 32; kt++) {
        __syncthreads();
        // Load K (transposed) and V tiles
#pragma unroll
        for (int it = 0; it < 4; it++) {
            int idx = tid + it * 256;
            int r = idx >> 4;
            int c4 = (idx & 15) * 4;
            float4 kv = *(const float4*)(Kg + (size_t)(kt * 64 + r) * 512 + c4);
            Kt[(c4 + 0) * 68 + r] = kv.x;
            Kt[(c4 + 1) * 68 + r] = kv.y;
            Kt[(c4 + 2) * 68 + r] = kv.z;
            Kt[(c4 + 3) * 68 + r] = kv.w;
            float4 vv = *(const float4*)(Vg + (size_t)(kt * 64 + r) * 512 + c4);
            *(float4*)(Vs + r * 68 + c4) = vv;
        }
        __syncthreads();

        // S = (Q*scale) @ K^T : 4x4 per thread via f32x2 pairs
        ull s2[4][2];
#pragma unroll
        for (int i = 0; i < 4; i++) { s2[i][0] = 0ull; s2[i][1] = 0ull; }

#pragma unroll
        for (int d = 0; d < 64; d++) {
            float4 qv = *(const float4*)(Qt + d * 68 + ty * 4);
            ull q0 = dup2(qv.x), q1 = dup2(qv.y), q2 = dup2(qv.z), q3 = dup2(qv.w);
            ull k0 = *(const ull*)(Kt + d * 68 + kcol);
            ull k1 = *(const ull*)(Kt + d * 68 + kcol + 2);
            s2[0][0] = fma2(q0, k0, s2[0][0]);
            s2[0][1] = fma2(q0, k1, s2[0][1]);
            s2[1][0] = fma2(q1, k0, s2[1][0]);
            s2[1][1] = fma2(q1, k1, s2[1][1]);
            s2[2][0] = fma2(q2, k0, s2[2][0]);
            s2[2][1] = fma2(q2, k1, s2[2][1]);
            s2[3][0] = fma2(q3, k0, s2[3][0]);
            s2[3][1] = fma2(q3, k1, s2[3][1]);
        }

        // Online softmax
        float s[4][4];
#pragma unroll
        for (int i = 0; i < 4; i++) {
            float2 p0 = unpk2(s2[i][0]), p1 = unpk2(s2[i][1]);
            s[i][0] = p0.x; s[i][1] = p0.y; s[i][2] = p1.x; s[i][3] = p1.y;
        }
#pragma unroll
        for (int i = 0; i < 4; i++) {
            float rm = fmaxf(fmaxf(s[i][0], s[i][1]), fmaxf(s[i][2], s[i][3]));
#pragma unroll
            for (int off = 8; off >= 1; off >>= 1)
                rm = fmaxf(rm, __shfl_xor_sync(0xffffffffu, rm, off));
            float mn = fmaxf(m[i], rm);
            float alpha = __expf(m[i] - mn);
            m[i] = mn;
            float rs = 0.0f;
#pragma unroll
            for (int j = 0; j < 4; j++) {
                float p = __expf(s[i][j] - mn);
                s[i][j] = p;
                rs += p;
            }
#pragma unroll
            for (int off = 8; off >= 1; off >>= 1)
                rs += __shfl_xor_sync(0xffffffffu, rs, off);
            l[i] = l[i] * alpha + rs;
            ull a2 = dup2(alpha);
            o2[i][0] = mul2(o2[i][0], a2);
            o2[i][1] = mul2(o2[i][1], a2);
        }

        // P -> smem [kj][q] stride 65
#pragma unroll
        for (int j = 0; j < 4; j++)
#pragma unroll
            for (int i = 0; i < 4; i++)
                Ps[(tx * 4 + j) * 65 + ty * 4 + i] = s[i][j];
        __syncthreads();

        // O += P @ V (f32x2)
#pragma unroll
        for (int kj = 0; kj < 64; kj++) {
            ull v0 = *(const ull*)(Vs + kj * 68 + kcol);
            ull v1 = *(const ull*)(Vs + kj * 68 + kcol + 2);
            ull p0 = dup2(Ps[kj * 65 + ty * 4 + 0]);
            ull p1 = dup2(Ps[kj * 65 + ty * 4 + 1]);
            ull p2 = dup2(Ps[kj * 65 + ty * 4 + 2]);
            ull p3 = dup2(Ps[kj * 65 + ty * 4 + 3]);
            o2[0][0] = fma2(p0, v0, o2[0][0]);
            o2[0][1] = fma2(p0, v1, o2[0][1]);
            o2[1][0] = fma2(p1, v0, o2[1][0]);
            o2[1][1] = fma2(p1, v1, o2[1][1]);
            o2[2][0] = fma2(p2, v0, o2[2][0]);
            o2[2][1] = fma2(p2, v1, o2[2][1]);
            o2[3][0] = fma2(p3, v0, o2[3][0]);
            o2[3][1] = fma2(p3, v1, o2[3][1]);
        }
    }

    // Normalize + write context
    float* Og = O + (size_t)(b * 2048 + qt * 64) * 2048 + h * 64;
#pragma unroll
    for (int i = 0; i < 4; i++) {
        float inv = 1.0f / l[i];
        float2 a = unpk2(o2[i][0]);
        float2 c = unpk2(o2[i][1]);
        *(float4*)(Og + (size_t)(ty * 4 + i) * 2048 + tx * 4) =
            make_float4(a.x * inv, a.y * inv, c.x * inv, c.y * inv);
    }
}

// ---------------------------------------------------------------------------
// Launch
// ---------------------------------------------------------------------------
extern "C" void kernel_launch(void* const* d_in, const int* in_sizes, int n_in,
                              void* d_out, int out_size) {
    const float* x  = (const float*)d_in[0];
    const float* Wq = (const float*)d_in[1];
    const float* Wk = (const float*)d_in[2];
    const float* Wv = (const float*)d_in[3];
    const float* Wo = (const float*)d_in[4];
    float* out = (float*)d_out;

    float *pQ, *pK, *pV, *pC;
    cudaGetSymbolAddress((void**)&pQ, g_Q);
    cudaGetSymbolAddress((void**)&pK, g_K);
    cudaGetSymbolAddress((void**)&pV, g_V);
    cudaGetSymbolAddress((void**)&pC, g_C);

    const int ATTN_SMEM = (64 * 68 * 3 + 64 * 65) * 4;
    cudaFuncSetAttribute(attn64, cudaFuncAttributeMaxDynamicSharedMemorySize,
                         ATTN_SMEM);

    // QKV projections
    sgemm128<<<dim3(16, 32), 256>>>(x, Wq, pQ, 4096, 2048, 2048);
    sgemm128<<<dim3(4, 32), 256>>>(x, Wk, pK, 4096, 512, 2048);
    sgemm128<<<dim3(4, 32), 256>>>(x, Wv, pV, 4096, 512, 2048);

    // Attention
    attn64<<<dim3(32, 64), 256, ATTN_SMEM>>>(pQ, pK, pV, pC);

    // Output projection
    sgemm128<<<dim3(16, 32), 256>>>(pC, Wo, out, 4096, 2048, 2048);
}